// round 2
// baseline (speedup 1.0000x reference)
#include <cuda_runtime.h>
#include <math.h>

// ---------------- dims ----------------
namespace {
constexpr int Bn  = 8;
constexpr int Nn  = 196;
constexpr int Dn  = 128;
constexpr int PDn = 256;
constexpr int DFFn= 256;
constexpr int Cn  = 1000;
constexpr int RALL = Bn * Nn;   // 1568

// ---------------- scratch (__device__ globals; no allocs allowed) ----------------
__device__ float g_patches[Bn * Nn * PDn];
__device__ float g_H   [RALL * Dn];
__device__ float g_QKV [3 * RALL * Dn];
__device__ float g_S   [Bn * Nn * Nn];
__device__ float g_ATT [RALL * Dn];
__device__ float g_FFH [RALL * DFFn];
__device__ float g_FFO [RALL * Dn];
__device__ float g_m   [RALL];
__device__ float g_ms  [RALL];
__device__ float g_Wqkv[2 * 3 * Dn * Dn];

// ---------------- patchify: (B,224,224) -> (B,196,256) ----------------
__global__ void patchify_k(const float* __restrict__ x) {
    int idx = blockIdx.x * 256 + threadIdx.x;
    if (idx >= Bn * Nn * PDn) return;
    int pd = idx & 255;
    int n  = (idx >> 8) % Nn;
    int b  = idx / (Nn * PDn);
    int p1 = pd >> 4, p2 = pd & 15;
    int g1 = n / 14,  g2 = n % 14;
    g_patches[idx] = x[((size_t)b * 224 + g1 * 16 + p1) * 224 + g2 * 16 + p2];
}

// ---------------- concat qkv weights for both layers into one buffer ----------------
struct W6 { const float* p[6]; };
__global__ void concat_k(W6 w) {
    int idx = blockIdx.x * 256 + threadIdx.x;
    if (idx >= 6 * Dn * Dn) return;
    g_Wqkv[idx] = w.p[idx >> 14][idx & (Dn * Dn - 1)];
}

// ---------------- generic tiled tropical GEMM ----------------
// Y[r,i] = max_j ( X[r,j] + (NT ? W[i,j] : W[j,i]) )   + epilogue
// EPI: 0 none | 1 +pos[(r%196)*Dn+i] | 2 -m[r] | 3 max(v - m[r], tau)
template<int EPI, bool NT>
__global__ __launch_bounds__(256) void tg(
    const float* __restrict__ Xg, const float* __restrict__ Wg, float* __restrict__ Yg,
    int R, int I, int J, int sx, int sw, int sy,
    const float* __restrict__ mg, int sm,
    const float* __restrict__ pos, const float* __restrict__ taup)
{
    __shared__ float Xs[16 * 68];
    __shared__ float Ws[16 * 68];

    const int b = blockIdx.z;
    const float* X = Xg + (size_t)b * sx;
    const float* W = Wg + (size_t)b * sw;
    float*       Y = Yg + (size_t)b * sy;

    const int row0 = blockIdx.y * 64;
    const int i0   = blockIdx.x * 64;
    const int t  = threadIdx.x;
    const int cx = t & 15;        // output col group
    const int cy = t >> 4;        // output row group

    float acc[4][4];
#pragma unroll
    for (int u = 0; u < 4; ++u)
#pragma unroll
        for (int v = 0; v < 4; ++v) acc[u][v] = -INFINITY;

    const int lr  = t >> 2;          // 0..63 (row/col-of-operand loader)
    const int ljq = (t & 3) * 4;     // 0,4,8,12
    const int lj_nn  = t >> 4;       // 0..15
    const int liq_nn = (t & 15) * 4; // 0..60

    for (int j0 = 0; j0 < J; j0 += 16) {
        // load X tile (transposed to j-major)
        {
            int gr = min(row0 + lr, R - 1);
            const float* xr = X + (size_t)gr * J;
            int jb = j0 + ljq;
            float4 v;
            if (jb + 3 < J) v = *(const float4*)(xr + jb);
            else {
                v.x = xr[min(jb + 0, J - 1)];
                v.y = xr[min(jb + 1, J - 1)];
                v.z = xr[min(jb + 2, J - 1)];
                v.w = xr[min(jb + 3, J - 1)];
            }
            Xs[(ljq + 0) * 68 + lr] = v.x;
            Xs[(ljq + 1) * 68 + lr] = v.y;
            Xs[(ljq + 2) * 68 + lr] = v.z;
            Xs[(ljq + 3) * 68 + lr] = v.w;
        }
        if (NT) {
            int gi = min(i0 + lr, I - 1);
            const float* wr = W + (size_t)gi * J;
            int jb = j0 + ljq;
            float4 v;
            if (jb + 3 < J) v = *(const float4*)(wr + jb);
            else {
                v.x = wr[min(jb + 0, J - 1)];
                v.y = wr[min(jb + 1, J - 1)];
                v.z = wr[min(jb + 2, J - 1)];
                v.w = wr[min(jb + 3, J - 1)];
            }
            Ws[(ljq + 0) * 68 + lr] = v.x;
            Ws[(ljq + 1) * 68 + lr] = v.y;
            Ws[(ljq + 2) * 68 + lr] = v.z;
            Ws[(ljq + 3) * 68 + lr] = v.w;
        } else {
            int gj = min(j0 + lj_nn, J - 1);
            const float* wr = W + (size_t)gj * I;
            int ib = i0 + liq_nn;
            float4 v;
            if (ib + 3 < I) v = *(const float4*)(wr + ib);
            else {
                v.x = wr[min(ib + 0, I - 1)];
                v.y = wr[min(ib + 1, I - 1)];
                v.z = wr[min(ib + 2, I - 1)];
                v.w = wr[min(ib + 3, I - 1)];
            }
            *(float4*)&Ws[lj_nn * 68 + liq_nn] = v;
        }
        __syncthreads();

#pragma unroll
        for (int jj = 0; jj < 16; ++jj) {
            float4 a  = *(const float4*)&Xs[jj * 68 + cy * 4];
            float4 bb = *(const float4*)&Ws[jj * 68 + cx * 4];
            float av[4] = {a.x, a.y, a.z, a.w};
            float bv[4] = {bb.x, bb.y, bb.z, bb.w};
#pragma unroll
            for (int u = 0; u < 4; ++u)
#pragma unroll
                for (int v = 0; v < 4; ++v)
                    acc[u][v] = fmaxf(acc[u][v], av[u] + bv[v]);
        }
        __syncthreads();
    }

    float tauv = 0.f;
    if (EPI == 3) tauv = __ldg(taup);
    const float* mb = (EPI == 2 || EPI == 3) ? (mg + (size_t)b * sm) : nullptr;

#pragma unroll
    for (int u = 0; u < 4; ++u) {
        int rr = row0 + cy * 4 + u;
        if (rr >= R) continue;
        float mv = 0.f;
        if (EPI == 2 || EPI == 3) mv = mb[rr];
        int nmod = 0;
        if (EPI == 1) nmod = rr % Nn;
#pragma unroll
        for (int v = 0; v < 4; ++v) {
            int ii = i0 + cx * 4 + v;
            if (ii >= I) continue;
            float val = acc[u][v];
            if (EPI == 1) val += pos[(size_t)nmod * Dn + ii];
            if (EPI == 2) val -= mv;
            if (EPI == 3) val = fmaxf(val - mv, tauv);
            Y[(size_t)rr * I + ii] = val;
        }
    }
}

// ---------------- row max over C cols ----------------
__global__ void rowmax_k(const float* __restrict__ X, float* __restrict__ m, int R, int Ccols) {
    int r = blockIdx.x * 8 + (threadIdx.x >> 5);
    if (r >= R) return;
    int lane = threadIdx.x & 31;
    const float* xr = X + (size_t)r * Ccols;
    float mx = -INFINITY;
    for (int c = lane; c < Ccols; c += 32) mx = fmaxf(mx, xr[c]);
#pragma unroll
    for (int o = 16; o > 0; o >>= 1) mx = fmaxf(mx, __shfl_xor_sync(0xffffffffu, mx, o));
    if (lane == 0) m[r] = mx;
}

// ---------------- H = max(H, A - rowmax(A)) , C = 128 ----------------
__global__ void fuse_k(float* __restrict__ H, const float* __restrict__ A, int R) {
    int r = blockIdx.x * 8 + (threadIdx.x >> 5);
    if (r >= R) return;
    int lane = threadIdx.x & 31;
    const float* ar = A + (size_t)r * Dn;
    float*       hr = H + (size_t)r * Dn;
    float a0 = ar[lane], a1 = ar[lane + 32], a2 = ar[lane + 64], a3 = ar[lane + 96];
    float mx = fmaxf(fmaxf(a0, a1), fmaxf(a2, a3));
#pragma unroll
    for (int o = 16; o > 0; o >>= 1) mx = fmaxf(mx, __shfl_xor_sync(0xffffffffu, mx, o));
    hr[lane]      = fmaxf(hr[lane],      a0 - mx);
    hr[lane + 32] = fmaxf(hr[lane + 32], a1 - mx);
    hr[lane + 64] = fmaxf(hr[lane + 64], a2 - mx);
    hr[lane + 96] = fmaxf(hr[lane + 96], a3 - mx);
}

// ---------------- pooled + head + scale ----------------
__global__ void head_k(const float* __restrict__ headW, const float* __restrict__ lsc,
                       float* __restrict__ out) {
    __shared__ float pooled[Dn];
    int b = blockIdx.x, t = threadIdx.x;
    if (t < Dn) {
        float mx = -INFINITY;
        const float* hb = g_H + (size_t)b * Nn * Dn + t;
        for (int n = 0; n < Nn; ++n) mx = fmaxf(mx, hb[(size_t)n * Dn]);
        pooled[t] = mx;
    }
    __syncthreads();
    float s = __ldg(lsc);
    for (int c = t; c < Cn; c += 256) {
        const float* wr = headW + (size_t)c * Dn;
        float mx = -INFINITY;
#pragma unroll 4
        for (int d = 0; d < Dn; ++d) mx = fmaxf(mx, pooled[d] + wr[d]);
        out[(size_t)b * Cn + c] = mx * s;
    }
}

} // namespace

// ---------------- driver ----------------
extern "C" void kernel_launch(void* const* d_in, const int* in_sizes, int n_in,
                              void* d_out, int out_size) {
    (void)in_sizes; (void)n_in; (void)out_size;
    const float* x      = (const float*)d_in[0];
    const float* embedW = (const float*)d_in[1];
    const float* pos    = (const float*)d_in[2];
    const float* qW[2]  = {(const float*)d_in[3],  (const float*)d_in[9]};
    const float* kW[2]  = {(const float*)d_in[4],  (const float*)d_in[10]};
    const float* vW[2]  = {(const float*)d_in[5],  (const float*)d_in[11]};
    const float* f1W[2] = {(const float*)d_in[6],  (const float*)d_in[12]};
    const float* f2W[2] = {(const float*)d_in[7],  (const float*)d_in[13]};
    const float* tau[2] = {(const float*)d_in[8],  (const float*)d_in[14]};
    const float* headW  = (const float*)d_in[15];
    const float* lsc    = (const float*)d_in[16];
    float* out = (float*)d_out;

    void *pPat, *pH, *pQKV, *pS, *pATT, *pFFH, *pFFO, *pM, *pMS, *pWq;
    cudaGetSymbolAddress(&pPat, g_patches);
    cudaGetSymbolAddress(&pH,   g_H);
    cudaGetSymbolAddress(&pQKV, g_QKV);
    cudaGetSymbolAddress(&pS,   g_S);
    cudaGetSymbolAddress(&pATT, g_ATT);
    cudaGetSymbolAddress(&pFFH, g_FFH);
    cudaGetSymbolAddress(&pFFO, g_FFO);
    cudaGetSymbolAddress(&pM,   g_m);
    cudaGetSymbolAddress(&pMS,  g_ms);
    cudaGetSymbolAddress(&pWq,  g_Wqkv);

    const float* fH   = (const float*)pH;
    const float* fQKV = (const float*)pQKV;
    const float* fS   = (const float*)pS;
    const float* fFFH = (const float*)pFFH;

    patchify_k<<<(Bn * Nn * PDn + 255) / 256, 256>>>(x);

    W6 w6;
    w6.p[0] = qW[0]; w6.p[1] = kW[0]; w6.p[2] = vW[0];
    w6.p[3] = qW[1]; w6.p[4] = kW[1]; w6.p[5] = vW[1];
    concat_k<<<(6 * Dn * Dn + 255) / 256, 256>>>(w6);

    // embed: H = tropmm(patches, embedW) + pos
    tg<1, true><<<dim3(2, 25, 1), 256>>>((const float*)pPat, embedW, (float*)pH,
        RALL, Dn, PDn, 0, 0, 0, nullptr, 0, pos, nullptr);

    const int rowBlocks = (RALL + 7) / 8;   // 196

    for (int l = 0; l < 2; ++l) {
        // m = rowmax(H)
        rowmax_k<<<rowBlocks, 256>>>(fH, (float*)pM, RALL, Dn);
        // q,k,v = tropmm(H, W) - m   (fused 3-slice launch)
        tg<2, true><<<dim3(2, 25, 3), 256>>>(fH, (const float*)pWq + (size_t)l * 3 * Dn * Dn,
            (float*)pQKV, RALL, Dn, Dn, 0, Dn * Dn, RALL * Dn, (const float*)pM, 0,
            nullptr, nullptr);
        // S[b,i,j] = max_d(q+k)
        tg<0, true><<<dim3(4, 4, 8), 256>>>(fQKV, fQKV + (size_t)RALL * Dn, (float*)pS,
            Nn, Nn, Dn, Nn * Dn, Nn * Dn, Nn * Nn, nullptr, 0, nullptr, nullptr);
        // ms = rowmax_j(S)
        rowmax_k<<<rowBlocks, 256>>>(fS, (float*)pMS, RALL, Nn);
        // ATT[b,i,d] = max_j(S + v) - ms
        tg<2, false><<<dim3(2, 4, 8), 256>>>(fS, fQKV + (size_t)2 * RALL * Dn, (float*)pATT,
            Nn, Dn, Nn, Nn * Nn, Nn * Dn, Nn * Dn, (const float*)pMS, Nn, nullptr, nullptr);
        // H = max(H, pnorm(ATT))
        fuse_k<<<rowBlocks, 256>>>((float*)pH, (const float*)pATT, RALL);
        // m2 = rowmax(H)
        rowmax_k<<<rowBlocks, 256>>>(fH, (float*)pM, RALL, Dn);
        // FFH = max(tropmm(H,f1) - m2, tau)
        tg<3, true><<<dim3(4, 25, 1), 256>>>(fH, f1W[l], (float*)pFFH,
            RALL, DFFn, Dn, 0, 0, 0, (const float*)pM, 0, nullptr, tau[l]);
        // FFO = tropmm(FFH, f2)
        tg<0, true><<<dim3(2, 25, 1), 256>>>(fFFH, f2W[l], (float*)pFFO,
            RALL, Dn, DFFn, 0, 0, 0, nullptr, 0, nullptr, nullptr);
        // H = max(H, pnorm(FFO))
        fuse_k<<<rowBlocks, 256>>>((float*)pH, (const float*)pFFO, RALL);
    }

    head_k<<<Bn, 256>>>(headW, lsc, out);
}

// round 3
// speedup vs baseline: 1.3525x; 1.3525x over previous
#include <cuda_runtime.h>
#include <math.h>

namespace {
constexpr int Bn  = 8;
constexpr int Nn  = 196;
constexpr int Dn  = 128;
constexpr int PDn = 256;
constexpr int DFFn= 256;
constexpr int Cn  = 1000;
constexpr int RALL = Bn * Nn;   // 1568

// ---------------- scratch ----------------
__device__ float g_patches[Bn * Nn * PDn];
__device__ float g_H   [RALL * Dn];
__device__ float g_QKV [3 * RALL * Dn];
__device__ float g_S   [Bn * Nn * Nn];
__device__ float g_FFH [RALL * DFFn];
__device__ float g_Wqkv[2 * 3 * Dn * Dn];

// ---------------- prep: patchify + qkv-weight concat in one launch ----------------
struct W6 { const float* p[6]; };
__global__ void prep_k(const float* __restrict__ x, W6 w) {
    int idx = blockIdx.x * 256 + threadIdx.x;
    const int NP = Bn * Nn * PDn;
    if (idx < NP) {
        int pd = idx & 255;
        int n  = (idx >> 8) % Nn;
        int b  = idx / (Nn * PDn);
        int p1 = pd >> 4, p2 = pd & 15;
        int g1 = n / 14,  g2 = n % 14;
        g_patches[idx] = x[((size_t)b * 224 + g1 * 16 + p1) * 224 + g2 * 16 + p2];
    } else {
        int j = idx - NP;
        if (j < 6 * Dn * Dn) g_Wqkv[j] = w.p[j >> 14][j & (Dn * Dn - 1)];
    }
}

// ---------------- 64x64 tiled tropical GEMM (NT: W[i,j]) ----------------
// Y[r,i] = max_j( X[r,j] + W[i,j] ) + epilogue
// EPI: 0 none | 1 +pos | 2 -rowmaxX (computed in-kernel, X width 128)
//      3 max(v - rowmaxX, tau)
template<int EPI>
__global__ __launch_bounds__(256) void tg64(
    const float* __restrict__ Xg, const float* __restrict__ Wg, float* __restrict__ Yg,
    int R, int I, int J, int sx, int sw, int sy,
    const float* __restrict__ pos, const float* __restrict__ taup)
{
    __shared__ float Xs[16 * 68];
    __shared__ float Ws[16 * 68];
    __shared__ float m_s[64];

    const int b = blockIdx.z;
    const float* X = Xg + (size_t)b * sx;
    const float* W = Wg + (size_t)b * sw;
    float*       Y = Yg + (size_t)b * sy;

    const int row0 = blockIdx.y * 64;
    const int i0   = blockIdx.x * 64;
    const int t  = threadIdx.x;
    const int cx = t & 15;
    const int cy = t >> 4;

    if (EPI == 2 || EPI == 3) {
        // rowmax of X rows (X width == 128 here)
        int row = t >> 2, part = t & 3;
        int gr = min(row0 + row, R - 1);
        const float* xr = X + (size_t)gr * 128;
        float mx = -INFINITY;
#pragma unroll 8
        for (int c = part * 32; c < part * 32 + 32; ++c) mx = fmaxf(mx, xr[c]);
        mx = fmaxf(mx, __shfl_xor_sync(0xffffffffu, mx, 1));
        mx = fmaxf(mx, __shfl_xor_sync(0xffffffffu, mx, 2));
        if (part == 0) m_s[row] = mx;
        __syncthreads();
    }

    float acc[4][4];
#pragma unroll
    for (int u = 0; u < 4; ++u)
#pragma unroll
        for (int v = 0; v < 4; ++v) acc[u][v] = -INFINITY;

    const int lr  = t >> 2;
    const int ljq = (t & 3) * 4;

    for (int j0 = 0; j0 < J; j0 += 16) {
        {
            int gr = min(row0 + lr, R - 1);
            const float* xr = X + (size_t)gr * J;
            float4 v = *(const float4*)(xr + j0 + ljq);
            Xs[(ljq + 0) * 68 + lr] = v.x;
            Xs[(ljq + 1) * 68 + lr] = v.y;
            Xs[(ljq + 2) * 68 + lr] = v.z;
            Xs[(ljq + 3) * 68 + lr] = v.w;
        }
        {
            int gi = min(i0 + lr, I - 1);
            const float* wr = W + (size_t)gi * J;
            float4 v = *(const float4*)(wr + j0 + ljq);
            Ws[(ljq + 0) * 68 + lr] = v.x;
            Ws[(ljq + 1) * 68 + lr] = v.y;
            Ws[(ljq + 2) * 68 + lr] = v.z;
            Ws[(ljq + 3) * 68 + lr] = v.w;
        }
        __syncthreads();

#pragma unroll
        for (int jj = 0; jj < 16; ++jj) {
            float4 a  = *(const float4*)&Xs[jj * 68 + cy * 4];
            float4 bb = *(const float4*)&Ws[jj * 68 + cx * 4];
            float av[4] = {a.x, a.y, a.z, a.w};
            float bv[4] = {bb.x, bb.y, bb.z, bb.w};
#pragma unroll
            for (int u = 0; u < 4; ++u)
#pragma unroll
                for (int v = 0; v < 4; ++v)
                    acc[u][v] = fmaxf(acc[u][v], av[u] + bv[v]);
        }
        __syncthreads();
    }

    const float tauv = (EPI == 3) ? __ldg(taup) : 0.f;

#pragma unroll
    for (int u = 0; u < 4; ++u) {
        int rr = row0 + cy * 4 + u;
        if (rr >= R) continue;
        float mv = (EPI == 2 || EPI == 3) ? m_s[cy * 4 + u] : 0.f;
        int nmod = (EPI == 1) ? (rr % Nn) : 0;
#pragma unroll
        for (int v = 0; v < 4; ++v) {
            int ii = i0 + cx * 4 + v;
            if (ii >= I) continue;
            float val = acc[u][v];
            if (EPI == 1) val += pos[(size_t)nmod * Dn + ii];
            if (EPI == 2) val -= mv;
            if (EPI == 3) val = fmaxf(val - mv, tauv);
            Y[(size_t)rr * I + ii] = val;
        }
    }
}

// ---------------- full-width (16 x 128) tropical GEMM with fused pnorm+residual ----------------
// Z[r,i] = max_j( X[r,j] + W ) ;  H[r,i] = max(H[r,i], Z[r,i] - max_i Z[r,:])
// NT: W[i*J + j]  (ff2) ;  !NT: W[j*128 + i]  (attention SV, v rows)
template<bool NT>
__global__ __launch_bounds__(256) void tgfw(
    const float* __restrict__ Xg, const float* __restrict__ Wg, float* __restrict__ Hg,
    int R, int J, int ldx, int sx, int sy)
{
    __shared__ float Xs[16 * 16];
    __shared__ float Ws[16 * 128];

    const int b = blockIdx.y;
    const float* X = Xg + (size_t)b * sx;
    float*       H = Hg + (size_t)b * sy;
    const int row0 = blockIdx.x * 16;
    const int t = threadIdx.x;
    const int w = t >> 5, lane = t & 31;

    float acc[2][4];
#pragma unroll
    for (int u = 0; u < 2; ++u)
#pragma unroll
        for (int v = 0; v < 4; ++v) acc[u][v] = -INFINITY;

    for (int j0 = 0; j0 < J; j0 += 16) {
        {
            int jj = t >> 4, r = t & 15;
            int gj = min(j0 + jj, J - 1);
            int gr = min(row0 + r, R - 1);
            Xs[jj * 16 + r] = X[(size_t)gr * ldx + gj];
        }
        if (NT) {
            // W[i*J + j], J multiple of 16 (256). scatter-transpose.
            int i = t >> 1, jq = (t & 1) * 8;
            const float* wr = Wg + (size_t)i * J + j0 + jq;
            float4 a = *(const float4*)wr;
            float4 c = *(const float4*)(wr + 4);
            Ws[(jq + 0) * 128 + i] = a.x;
            Ws[(jq + 1) * 128 + i] = a.y;
            Ws[(jq + 2) * 128 + i] = a.z;
            Ws[(jq + 3) * 128 + i] = a.w;
            Ws[(jq + 4) * 128 + i] = c.x;
            Ws[(jq + 5) * 128 + i] = c.y;
            Ws[(jq + 6) * 128 + i] = c.z;
            Ws[(jq + 7) * 128 + i] = c.w;
        } else {
            const float* W = Wg + (size_t)b * (Nn * Dn);
#pragma unroll
            for (int rep = 0; rep < 2; ++rep) {
                int jj = (t >> 5) + rep * 8;
                int gj = min(j0 + jj, J - 1);
                float4 a = *(const float4*)(W + (size_t)gj * 128 + lane * 4);
                *(float4*)&Ws[jj * 128 + lane * 4] = a;
            }
        }
        __syncthreads();

#pragma unroll
        for (int jj = 0; jj < 16; ++jj) {
            float2 xv = *(const float2*)&Xs[jj * 16 + 2 * w];
            float4 wv = *(const float4*)&Ws[jj * 128 + lane * 4];
            acc[0][0] = fmaxf(acc[0][0], xv.x + wv.x);
            acc[0][1] = fmaxf(acc[0][1], xv.x + wv.y);
            acc[0][2] = fmaxf(acc[0][2], xv.x + wv.z);
            acc[0][3] = fmaxf(acc[0][3], xv.x + wv.w);
            acc[1][0] = fmaxf(acc[1][0], xv.y + wv.x);
            acc[1][1] = fmaxf(acc[1][1], xv.y + wv.y);
            acc[1][2] = fmaxf(acc[1][2], xv.y + wv.z);
            acc[1][3] = fmaxf(acc[1][3], xv.y + wv.w);
        }
        __syncthreads();
    }

#pragma unroll
    for (int u = 0; u < 2; ++u) {
        int rr = row0 + 2 * w + u;
        float rmx = fmaxf(fmaxf(acc[u][0], acc[u][1]), fmaxf(acc[u][2], acc[u][3]));
#pragma unroll
        for (int o = 16; o > 0; o >>= 1)
            rmx = fmaxf(rmx, __shfl_xor_sync(0xffffffffu, rmx, o));
        if (rr < R) {
            float* hr = H + (size_t)rr * 128 + lane * 4;
            float4 h = *(const float4*)hr;
            h.x = fmaxf(h.x, acc[u][0] - rmx);
            h.y = fmaxf(h.y, acc[u][1] - rmx);
            h.z = fmaxf(h.z, acc[u][2] - rmx);
            h.w = fmaxf(h.w, acc[u][3] - rmx);
            *(float4*)hr = h;
        }
    }
}

// ---------------- pooled + head + scale ----------------
__global__ void head_k(const float* __restrict__ headW, const float* __restrict__ lsc,
                       float* __restrict__ out) {
    __shared__ float pooled[Dn];
    int b = blockIdx.x, chunk = blockIdx.y, t = threadIdx.x;
    if (t < Dn) {
        float mx = -INFINITY;
        const float* hb = g_H + (size_t)b * Nn * Dn + t;
        for (int n = 0; n < Nn; ++n) mx = fmaxf(mx, hb[(size_t)n * Dn]);
        pooled[t] = mx;
    }
    __syncthreads();
    float s = __ldg(lsc);
    int c = chunk * 256 + t;
    if (c < Cn) {
        const float* wr = headW + (size_t)c * Dn;
        float mx = -INFINITY;
#pragma unroll 4
        for (int d = 0; d < Dn; ++d) mx = fmaxf(mx, pooled[d] + wr[d]);
        out[(size_t)b * Cn + c] = mx * s;
    }
}

} // namespace

// ---------------- driver ----------------
extern "C" void kernel_launch(void* const* d_in, const int* in_sizes, int n_in,
                              void* d_out, int out_size) {
    (void)in_sizes; (void)n_in; (void)out_size;
    const float* x      = (const float*)d_in[0];
    const float* embedW = (const float*)d_in[1];
    const float* pos    = (const float*)d_in[2];
    const float* qW[2]  = {(const float*)d_in[3],  (const float*)d_in[9]};
    const float* kW[2]  = {(const float*)d_in[4],  (const float*)d_in[10]};
    const float* vW[2]  = {(const float*)d_in[5],  (const float*)d_in[11]};
    const float* f1W[2] = {(const float*)d_in[6],  (const float*)d_in[12]};
    const float* f2W[2] = {(const float*)d_in[7],  (const float*)d_in[13]};
    const float* tau[2] = {(const float*)d_in[8],  (const float*)d_in[14]};
    const float* headW  = (const float*)d_in[15];
    const float* lsc    = (const float*)d_in[16];
    float* out = (float*)d_out;

    void *pPat, *pH, *pQKV, *pS, *pFFH, *pWq;
    cudaGetSymbolAddress(&pPat, g_patches);
    cudaGetSymbolAddress(&pH,   g_H);
    cudaGetSymbolAddress(&pQKV, g_QKV);
    cudaGetSymbolAddress(&pS,   g_S);
    cudaGetSymbolAddress(&pFFH, g_FFH);
    cudaGetSymbolAddress(&pWq,  g_Wqkv);

    const float* fH   = (const float*)pH;
    const float* fQKV = (const float*)pQKV;
    const float* fS   = (const float*)pS;
    const float* fFFH = (const float*)pFFH;

    // prep: patchify (401408) + concat (98304) = 499712 = 256*1952
    W6 w6;
    w6.p[0] = qW[0]; w6.p[1] = kW[0]; w6.p[2] = vW[0];
    w6.p[3] = qW[1]; w6.p[4] = kW[1]; w6.p[5] = vW[1];
    prep_k<<<1952, 256>>>(x, w6);

    // embed: H = tropmm(patches, embedW) + pos
    tg64<1><<<dim3(2, 25, 1), 256>>>((const float*)pPat, embedW, (float*)pH,
        RALL, Dn, PDn, 0, 0, 0, pos, nullptr);

    for (int l = 0; l < 2; ++l) {
        // q,k,v = tropmm(H, W) - rowmax(H)   (m computed in-kernel; 3 slices)
        tg64<2><<<dim3(2, 25, 3), 256>>>(fH,
            (const float*)pWq + (size_t)l * 3 * Dn * Dn, (float*)pQKV,
            RALL, Dn, Dn, 0, Dn * Dn, RALL * Dn, nullptr, nullptr);
        // S[b,i,j] = max_d(q_id + k_jd)   (raw; normalization cancels downstream)
        tg64<0><<<dim3(4, 4, 8), 256>>>(fQKV, fQKV + (size_t)RALL * Dn, (float*)pS,
            Nn, Nn, Dn, Nn * Dn, Nn * Dn, Nn * Nn, nullptr, nullptr);
        // Z = max_j(S + v) ;  H = max(H, Z - rowmax_d Z)
        tgfw<false><<<dim3(13, 8), 256>>>(fS, fQKV + (size_t)2 * RALL * Dn, (float*)pH,
            Nn, Nn, Nn, Nn * Nn, Nn * Dn);
        // FFH = max(tropmm(H, f1) - rowmax(H), tau)
        tg64<3><<<dim3(4, 25, 1), 256>>>(fH, f1W[l], (float*)pFFH,
            RALL, DFFn, Dn, 0, 0, 0, nullptr, tau[l]);
        // Z = tropmm(FFH, f2) ;  H = max(H, Z - rowmax_d Z)
        tgfw<true><<<dim3(98, 1), 256>>>(fFFH, f2W[l], (float*)pH,
            RALL, DFFn, DFFn, 0, 0);
    }

    head_k<<<dim3(8, 4), 256>>>(headW, lsc, out);
}

// round 4
// speedup vs baseline: 1.3865x; 1.0251x over previous
#include <cuda_runtime.h>
#include <math.h>

namespace {
constexpr int Bn  = 8;
constexpr int Nn  = 196;
constexpr int Dn  = 128;
constexpr int PDn = 256;
constexpr int DFFn= 256;
constexpr int Cn  = 1000;
constexpr int RALL = Bn * Nn;   // 1568

// ---------------- scratch ----------------
__device__ float g_patches[Bn * Nn * PDn];
__device__ float g_H   [RALL * Dn];
__device__ float g_QKV [3 * RALL * Dn];
__device__ float g_S   [Bn * Nn * Nn];
__device__ float g_FFH [RALL * DFFn];
__device__ float g_Wqkv[2 * 3 * Dn * Dn];

// ---------------- prep: patchify + qkv-weight concat ----------------
struct W6 { const float* p[6]; };
__global__ void prep_k(const float* __restrict__ x, W6 w) {
    int idx = blockIdx.x * 256 + threadIdx.x;
    const int NP = Bn * Nn * PDn;
    if (idx < NP) {
        int pd = idx & 255;
        int n  = (idx >> 8) % Nn;
        int b  = idx / (Nn * PDn);
        int p1 = pd >> 4, p2 = pd & 15;
        int g1 = n / 14,  g2 = n % 14;
        g_patches[idx] = x[((size_t)b * 224 + g1 * 16 + p1) * 224 + g2 * 16 + p2];
    } else {
        int j = idx - NP;
        if (j < 6 * Dn * Dn) g_Wqkv[j] = w.p[j >> 14][j & (Dn * Dn - 1)];
    }
}

// ---------------- 32x64 tiled tropical GEMM (NT layout: W[i,j]) ----------------
// Y[r,i] = max_j( X[r,j] + W[i,j] ) + epilogue
// EPI: 0 none | 1 +pos | 2 -rowmaxX (in-kernel, X width 128) | 3 max(v-rowmaxX, tau)
template<int EPI>
__global__ __launch_bounds__(256) void tg32(
    const float* __restrict__ Xg, const float* __restrict__ Wg, float* __restrict__ Yg,
    int R, int I, int J, int sx, int sw, int sy,
    const float* __restrict__ pos, const float* __restrict__ taup)
{
    __shared__ float Xs[16 * 36];
    __shared__ float Ws[16 * 68];
    __shared__ float m_s[32];

    const int b = blockIdx.z;
    const float* X = Xg + (size_t)b * sx;
    const float* W = Wg + (size_t)b * sw;
    float*       Y = Yg + (size_t)b * sy;

    const int row0 = blockIdx.y * 32;
    const int i0   = blockIdx.x * 64;
    const int t  = threadIdx.x;
    const int cx = t & 15;        // col group (4 cols)
    const int cy = t >> 4;        // row group (2 rows)

    if (EPI == 2 || EPI == 3) {
        // rowmax of the 32 X rows (X width == 128 for these stages)
        int row = t >> 3, part = t & 7;
        int gr = min(row0 + row, R - 1);
        const float* xr = X + (size_t)gr * 128;
        float mx = -INFINITY;
#pragma unroll
        for (int c = part * 16; c < part * 16 + 16; ++c) mx = fmaxf(mx, xr[c]);
        mx = fmaxf(mx, __shfl_xor_sync(0xffffffffu, mx, 1));
        mx = fmaxf(mx, __shfl_xor_sync(0xffffffffu, mx, 2));
        mx = fmaxf(mx, __shfl_xor_sync(0xffffffffu, mx, 4));
        if (part == 0) m_s[row] = mx;
        __syncthreads();
    }

    float acc[2][4];
#pragma unroll
    for (int u = 0; u < 2; ++u)
#pragma unroll
        for (int v = 0; v < 4; ++v) acc[u][v] = -INFINITY;

    const int lrx = t >> 3;          // 0..31  X row
    const int jqx = (t & 7) * 2;     // j pair
    const int lrw = t >> 2;          // 0..63  W row
    const int jqw = (t & 3) * 4;     // j quad

    for (int j0 = 0; j0 < J; j0 += 16) {
        {
            int gr = min(row0 + lrx, R - 1);
            float2 v = *(const float2*)(X + (size_t)gr * J + j0 + jqx);
            Xs[(jqx + 0) * 36 + lrx] = v.x;
            Xs[(jqx + 1) * 36 + lrx] = v.y;
        }
        {
            int gi = min(i0 + lrw, I - 1);
            float4 v = *(const float4*)(W + (size_t)gi * J + j0 + jqw);
            Ws[(jqw + 0) * 68 + lrw] = v.x;
            Ws[(jqw + 1) * 68 + lrw] = v.y;
            Ws[(jqw + 2) * 68 + lrw] = v.z;
            Ws[(jqw + 3) * 68 + lrw] = v.w;
        }
        __syncthreads();

#pragma unroll
        for (int jj = 0; jj < 16; ++jj) {
            float2 a  = *(const float2*)&Xs[jj * 36 + cy * 2];
            float4 bb = *(const float4*)&Ws[jj * 68 + cx * 4];
            acc[0][0] = fmaxf(acc[0][0], a.x + bb.x);
            acc[0][1] = fmaxf(acc[0][1], a.x + bb.y);
            acc[0][2] = fmaxf(acc[0][2], a.x + bb.z);
            acc[0][3] = fmaxf(acc[0][3], a.x + bb.w);
            acc[1][0] = fmaxf(acc[1][0], a.y + bb.x);
            acc[1][1] = fmaxf(acc[1][1], a.y + bb.y);
            acc[1][2] = fmaxf(acc[1][2], a.y + bb.z);
            acc[1][3] = fmaxf(acc[1][3], a.y + bb.w);
        }
        __syncthreads();
    }

    const float tauv = (EPI == 3) ? __ldg(taup) : 0.f;

#pragma unroll
    for (int u = 0; u < 2; ++u) {
        int rr = row0 + cy * 2 + u;
        if (rr >= R) continue;
        float mv = (EPI == 2 || EPI == 3) ? m_s[cy * 2 + u] : 0.f;
        int nmod = (EPI == 1) ? (rr % Nn) : 0;
#pragma unroll
        for (int v = 0; v < 4; ++v) {
            int ii = i0 + cx * 4 + v;
            if (ii >= I) continue;
            float val = acc[u][v];
            if (EPI == 1) val += pos[(size_t)nmod * Dn + ii];
            if (EPI == 2) val -= mv;
            if (EPI == 3) val = fmaxf(val - mv, tauv);
            Y[(size_t)rr * I + ii] = val;
        }
    }
}

// ---------------- full-width (8 x 128) tropical GEMM, fused pnorm + residual ----------------
// Z[r,i] = max_j( X[r,j] + W ) ;  H[r,i] = max(H[r,i], Z[r,i] - max_i Z[r,:])
// NT: W[i*J + j] (ff2) ;  !NT: W[j*128 + i] per-batch (attention SV)
template<bool NT>
__global__ __launch_bounds__(256) void tgfw(
    const float* __restrict__ Xg, const float* __restrict__ Wg, float* __restrict__ Hg,
    int R, int J, int ldx, int sx, int sy)
{
    __shared__ float Xs[16 * 8];
    __shared__ float Ws[16 * 128];

    const int b = blockIdx.y;
    const float* X = Xg + (size_t)b * sx;
    float*       H = Hg + (size_t)b * sy;
    const int row0 = blockIdx.x * 8;
    const int t = threadIdx.x;
    const int w = t >> 5, lane = t & 31;

    float acc[4];
#pragma unroll
    for (int v = 0; v < 4; ++v) acc[v] = -INFINITY;

    for (int j0 = 0; j0 < J; j0 += 16) {
        if (t < 128) {
            int jj = t >> 3, r = t & 7;
            int gj = min(j0 + jj, J - 1);
            int gr = min(row0 + r, R - 1);
            Xs[jj * 8 + r] = X[(size_t)gr * ldx + gj];
        }
        if (NT) {
            int i = t >> 1, jq = (t & 1) * 8;
            const float* wr = Wg + (size_t)i * J + j0 + jq;
            float4 a = *(const float4*)wr;
            float4 c = *(const float4*)(wr + 4);
            Ws[(jq + 0) * 128 + i] = a.x;
            Ws[(jq + 1) * 128 + i] = a.y;
            Ws[(jq + 2) * 128 + i] = a.z;
            Ws[(jq + 3) * 128 + i] = a.w;
            Ws[(jq + 4) * 128 + i] = c.x;
            Ws[(jq + 5) * 128 + i] = c.y;
            Ws[(jq + 6) * 128 + i] = c.z;
            Ws[(jq + 7) * 128 + i] = c.w;
        } else {
            const float* W = Wg + (size_t)b * (Nn * Dn);
#pragma unroll
            for (int rep = 0; rep < 2; ++rep) {
                int jj = (t >> 5) + rep * 8;
                int gj = min(j0 + jj, J - 1);
                float4 a = *(const float4*)(W + (size_t)gj * 128 + lane * 4);
                *(float4*)&Ws[jj * 128 + lane * 4] = a;
            }
        }
        __syncthreads();

#pragma unroll
        for (int jj = 0; jj < 16; ++jj) {
            float xv = Xs[jj * 8 + w];
            float4 wv = *(const float4*)&Ws[jj * 128 + lane * 4];
            acc[0] = fmaxf(acc[0], xv + wv.x);
            acc[1] = fmaxf(acc[1], xv + wv.y);
            acc[2] = fmaxf(acc[2], xv + wv.z);
            acc[3] = fmaxf(acc[3], xv + wv.w);
        }
        __syncthreads();
    }

    int rr = row0 + w;
    float rmx = fmaxf(fmaxf(acc[0], acc[1]), fmaxf(acc[2], acc[3]));
#pragma unroll
    for (int o = 16; o > 0; o >>= 1)
        rmx = fmaxf(rmx, __shfl_xor_sync(0xffffffffu, rmx, o));
    if (rr < R) {
        float* hr = H + (size_t)rr * 128 + lane * 4;
        float4 h = *(const float4*)hr;
        h.x = fmaxf(h.x, acc[0] - rmx);
        h.y = fmaxf(h.y, acc[1] - rmx);
        h.z = fmaxf(h.z, acc[2] - rmx);
        h.w = fmaxf(h.w, acc[3] - rmx);
        *(float4*)hr = h;
    }
}

// ---------------- pooled + head + scale ----------------
__global__ void head_k(const float* __restrict__ headW, const float* __restrict__ lsc,
                       float* __restrict__ out) {
    __shared__ float pooled[Dn];
    int b = blockIdx.x, chunk = blockIdx.y, t = threadIdx.x;
    if (t < Dn) {
        float mx = -INFINITY;
        const float* hb = g_H + (size_t)b * Nn * Dn + t;
        for (int n = 0; n < Nn; ++n) mx = fmaxf(mx, hb[(size_t)n * Dn]);
        pooled[t] = mx;
    }
    __syncthreads();
    float s = __ldg(lsc);
    int c = chunk * 256 + t;
    if (c < Cn) {
        const float* wr = headW + (size_t)c * Dn;
        float mx = -INFINITY;
#pragma unroll 4
        for (int d = 0; d < Dn; ++d) mx = fmaxf(mx, pooled[d] + wr[d]);
        out[(size_t)b * Cn + c] = mx * s;
    }
}

} // namespace

// ---------------- driver ----------------
extern "C" void kernel_launch(void* const* d_in, const int* in_sizes, int n_in,
                              void* d_out, int out_size) {
    (void)in_sizes; (void)n_in; (void)out_size;
    const float* x      = (const float*)d_in[0];
    const float* embedW = (const float*)d_in[1];
    const float* pos    = (const float*)d_in[2];
    const float* qW[2]  = {(const float*)d_in[3],  (const float*)d_in[9]};
    const float* kW[2]  = {(const float*)d_in[4],  (const float*)d_in[10]};
    const float* vW[2]  = {(const float*)d_in[5],  (const float*)d_in[11]};
    const float* f1W[2] = {(const float*)d_in[6],  (const float*)d_in[12]};
    const float* f2W[2] = {(const float*)d_in[7],  (const float*)d_in[13]};
    const float* tau[2] = {(const float*)d_in[8],  (const float*)d_in[14]};
    const float* headW  = (const float*)d_in[15];
    const float* lsc    = (const float*)d_in[16];
    float* out = (float*)d_out;

    void *pPat, *pH, *pQKV, *pS, *pFFH, *pWq;
    cudaGetSymbolAddress(&pPat, g_patches);
    cudaGetSymbolAddress(&pH,   g_H);
    cudaGetSymbolAddress(&pQKV, g_QKV);
    cudaGetSymbolAddress(&pS,   g_S);
    cudaGetSymbolAddress(&pFFH, g_FFH);
    cudaGetSymbolAddress(&pWq,  g_Wqkv);

    const float* fH   = (const float*)pH;
    const float* fQKV = (const float*)pQKV;
    const float* fS   = (const float*)pS;
    const float* fFFH = (const float*)pFFH;

    W6 w6;
    w6.p[0] = qW[0]; w6.p[1] = kW[0]; w6.p[2] = vW[0];
    w6.p[3] = qW[1]; w6.p[4] = kW[1]; w6.p[5] = vW[1];
    prep_k<<<1952, 256>>>(x, w6);

    // embed: H = tropmm(patches, embedW) + pos       (grid 98)
    tg32<1><<<dim3(2, 49, 1), 256>>>((const float*)pPat, embedW, (float*)pH,
        RALL, Dn, PDn, 0, 0, 0, pos, nullptr);

    for (int l = 0; l < 2; ++l) {
        // q,k,v = tropmm(H, W) - rowmax(H)           (grid 294)
        tg32<2><<<dim3(2, 49, 3), 256>>>(fH,
            (const float*)pWq + (size_t)l * 3 * Dn * Dn, (float*)pQKV,
            RALL, Dn, Dn, 0, Dn * Dn, RALL * Dn, nullptr, nullptr);
        // S[b,i,j] = max_d(q_id + k_jd)              (grid 224)
        tg32<0><<<dim3(4, 7, 8), 256>>>(fQKV, fQKV + (size_t)RALL * Dn, (float*)pS,
            Nn, Nn, Dn, Nn * Dn, Nn * Dn, Nn * Nn, nullptr, nullptr);
        // Z = max_j(S + v); H = max(H, Z - rowmax Z) (grid 200)
        tgfw<false><<<dim3(25, 8), 256>>>(fS, fQKV + (size_t)2 * RALL * Dn, (float*)pH,
            Nn, Nn, Nn, Nn * Nn, Nn * Dn);
        // FFH = max(tropmm(H, f1) - rowmax(H), tau)  (grid 196)
        tg32<3><<<dim3(4, 49, 1), 256>>>(fH, f1W[l], (float*)pFFH,
            RALL, DFFn, Dn, 0, 0, 0, nullptr, tau[l]);
        // Z = tropmm(FFH, f2); H = max(H, Z - rowmax Z)  (grid 196)
        tgfw<true><<<dim3(196, 1), 256>>>(fFFH, f2W[l], (float*)pH,
            RALL, DFFn, DFFn, 0, 0);
    }

    head_k<<<dim3(8, 4), 256>>>(headW, lsc, out);
}

// round 5
// speedup vs baseline: 1.5039x; 1.0847x over previous
#include <cuda_runtime.h>
#include <math.h>

namespace {
constexpr int Bn  = 8;
constexpr int Nn  = 196;
constexpr int Dn  = 128;
constexpr int DFFn= 256;
constexpr int Cn  = 1000;
constexpr int RALL = Bn * Nn;   // 1568

// ---------------- scratch ----------------
__device__ float g_H   [RALL * Dn];
__device__ float g_QKV [3 * RALL * Dn];
__device__ float g_S   [Bn * Nn * Nn];
__device__ float g_FFH [RALL * DFFn];
__device__ float g_Wqkv[2 * 3 * Dn * Dn];

// ---------------- prep: qkv-weight concat ----------------
struct W6 { const float* p[6]; };
__global__ void prep_k(W6 w) {
    int idx = blockIdx.x * 256 + threadIdx.x;
    if (idx < 6 * Dn * Dn) g_Wqkv[idx] = w.p[idx >> 14][idx & (Dn * Dn - 1)];
}

// ---------------- 32 x TI tiled tropical GEMM, double-buffered, 128 threads ----------------
// Y[r,i] = max_j( X[r,j] + W[i,j] ) + epilogue
// EPI: 0 none | 1 +pos, X gathered from image (patchify fused) |
//      2 -rowmaxX (in-kernel, X width == J == 128) | 3 max(v - rowmaxX, tau)
template<int EPI, int TI>
__global__ __launch_bounds__(128) void tg32(
    const float* __restrict__ Xg, const float* __restrict__ Wg, float* __restrict__ Yg,
    int R, int I, int J, int sx, int sw, int sy,
    const float* __restrict__ pos, const float* __restrict__ taup,
    const float* __restrict__ xorig)
{
    constexpr int XST = 34;                  // even (float2 alignment), conflict-light STS
    constexpr int WST = (TI == 64) ? 72 : 36; // mult of 4 (float4 alignment), conflict-free LDS
    constexpr int NC  = TI / 8;              // cols per thread (8 or 4)

    __shared__ float Xs[2][32 * XST];
    __shared__ float Ws[2][32 * WST];
    __shared__ float m_s[32];

    const int b = blockIdx.z;
    const float* X = Xg + (size_t)b * sx;
    const float* W = Wg + (size_t)b * sw;
    float*       Y = Yg + (size_t)b * sy;

    const int row0 = blockIdx.y * 32;
    const int i0   = blockIdx.x * TI;
    const int t  = threadIdx.x;
    const int cx = t & 7;         // col group
    const int cy = t >> 3;        // row group (2 rows)

    // loader mapping
    const int lrx = t >> 2;                       // X row 0..31
    const int jqx = (t & 3) * 8;                  // j offset
    const int lrw = (TI == 64) ? (t >> 1) : (t >> 2);      // W row (i)
    const int jqw = (TI == 64) ? ((t & 1) * 16) : ((t & 3) * 8);
    const int grx = min(row0 + lrx, R - 1);
    const int giw = min(i0 + lrw, I - 1);

    // rowmax prologue (X width == 128 for these stages)
    if (EPI == 2 || EPI == 3) {
        int row = t >> 2, part = t & 3;
        int gr = min(row0 + row, R - 1);
        const float* xr = X + (size_t)gr * 128 + part * 32;
        float mx = -INFINITY;
#pragma unroll
        for (int c = 0; c < 32; c += 4) {
            float4 v = *(const float4*)(xr + c);
            mx = fmaxf(mx, fmaxf(fmaxf(v.x, v.y), fmaxf(v.z, v.w)));
        }
        mx = fmaxf(mx, __shfl_xor_sync(0xffffffffu, mx, 1));
        mx = fmaxf(mx, __shfl_xor_sync(0xffffffffu, mx, 2));
        if (part == 0) m_s[row] = mx;
    }

    // patch-gather base for fused patchify (EPI 1)
    const float* xb = nullptr;
    if (EPI == 1) {
        int bb = grx / Nn, n = grx % Nn;
        int g1 = n / 14, g2 = n % 14;
        xb = xorig + ((size_t)(bb * 224 + g1 * 16)) * 224 + g2 * 16;
    }

    float4 xr0, xr1;
    float4 wr0, wr1, wr2, wr3;

    auto loadX = [&](int j0) {
        if (EPI == 1) {
            int j = j0 + jqx;
            xr0 = *(const float4*)(xb + (j >> 4) * 224 + (j & 15));
            j += 4;
            xr1 = *(const float4*)(xb + (j >> 4) * 224 + (j & 15));
        } else {
            const float* p = X + (size_t)grx * J + j0 + jqx;
            xr0 = *(const float4*)p;
            xr1 = *(const float4*)(p + 4);
        }
    };
    auto loadW = [&](int j0) {
        const float* p = W + (size_t)giw * J + j0 + jqw;
        wr0 = *(const float4*)p;
        wr1 = *(const float4*)(p + 4);
        if (TI == 64) {
            wr2 = *(const float4*)(p + 8);
            wr3 = *(const float4*)(p + 12);
        }
    };
    auto stXW = [&](int buf) {
        float xv[8] = {xr0.x, xr0.y, xr0.z, xr0.w, xr1.x, xr1.y, xr1.z, xr1.w};
#pragma unroll
        for (int k = 0; k < 8; ++k) Xs[buf][(jqx + k) * XST + lrx] = xv[k];
        float wv[16] = {wr0.x, wr0.y, wr0.z, wr0.w, wr1.x, wr1.y, wr1.z, wr1.w,
                        wr2.x, wr2.y, wr2.z, wr2.w, wr3.x, wr3.y, wr3.z, wr3.w};
        constexpr int NW = (TI == 64) ? 16 : 8;
#pragma unroll
        for (int k = 0; k < NW; ++k) Ws[buf][(jqw + k) * WST + lrw] = wv[k];
    };

    float acc[2][NC];
#pragma unroll
    for (int u = 0; u < 2; ++u)
#pragma unroll
        for (int v = 0; v < NC; ++v) acc[u][v] = -INFINITY;

    const int nsteps = J >> 5;     // J multiple of 32 everywhere
    loadX(0); loadW(0);
    stXW(0);
    __syncthreads();

    for (int s = 0; s < nsteps; ++s) {
        const int buf = s & 1;
        const bool more = (s + 1 < nsteps);
        if (more) { loadX((s + 1) << 5); loadW((s + 1) << 5); }

#pragma unroll 8
        for (int jj = 0; jj < 32; ++jj) {
            float2 a  = *(const float2*)&Xs[buf][jj * XST + cy * 2];
            float4 b0 = *(const float4*)&Ws[buf][jj * WST + cx * 4];
            acc[0][0] = fmaxf(acc[0][0], a.x + b0.x);
            acc[0][1] = fmaxf(acc[0][1], a.x + b0.y);
            acc[0][2] = fmaxf(acc[0][2], a.x + b0.z);
            acc[0][3] = fmaxf(acc[0][3], a.x + b0.w);
            acc[1][0] = fmaxf(acc[1][0], a.y + b0.x);
            acc[1][1] = fmaxf(acc[1][1], a.y + b0.y);
            acc[1][2] = fmaxf(acc[1][2], a.y + b0.z);
            acc[1][3] = fmaxf(acc[1][3], a.y + b0.w);
            if (TI == 64) {
                float4 b1 = *(const float4*)&Ws[buf][jj * WST + 32 + cx * 4];
                acc[0][4] = fmaxf(acc[0][4], a.x + b1.x);
                acc[0][5] = fmaxf(acc[0][5], a.x + b1.y);
                acc[0][6] = fmaxf(acc[0][6], a.x + b1.z);
                acc[0][7] = fmaxf(acc[0][7], a.x + b1.w);
                acc[1][4] = fmaxf(acc[1][4], a.y + b1.x);
                acc[1][5] = fmaxf(acc[1][5], a.y + b1.y);
                acc[1][6] = fmaxf(acc[1][6], a.y + b1.z);
                acc[1][7] = fmaxf(acc[1][7], a.y + b1.w);
            }
        }
        if (more) stXW(buf ^ 1);
        __syncthreads();
    }

    const float tauv = (EPI == 3) ? __ldg(taup) : 0.f;

#pragma unroll
    for (int u = 0; u < 2; ++u) {
        int rr = row0 + cy * 2 + u;
        if (rr >= R) continue;
        float mv = (EPI == 2 || EPI == 3) ? m_s[cy * 2 + u] : 0.f;
        const float* posr = (EPI == 1) ? (pos + (size_t)(rr % Nn) * Dn) : nullptr;
        float* yr = Y + (size_t)rr * I;
#pragma unroll
        for (int v = 0; v < NC; ++v) {
            int ii = i0 + ((TI == 64) ? ((v < 4) ? (cx * 4 + v) : (32 + cx * 4 + v - 4))
                                      : (cx * 4 + v));
            if (ii >= I) continue;
            float val = acc[u][v];
            if (EPI == 1) val += posr[ii];
            if (EPI == 2) val -= mv;
            if (EPI == 3) val = fmaxf(val - mv, tauv);
            yr[ii] = val;
        }
    }
}

// ---------------- full-width (8 x 128) tropical GEMM, fused pnorm + residual ----------------
template<bool NT>
__global__ __launch_bounds__(256) void tgfw(
    const float* __restrict__ Xg, const float* __restrict__ Wg, float* __restrict__ Hg,
    int R, int J, int ldx, int sx, int sy)
{
    __shared__ float Xs[16 * 8];
    __shared__ float Ws[16 * 128];

    const int b = blockIdx.y;
    const float* X = Xg + (size_t)b * sx;
    float*       H = Hg + (size_t)b * sy;
    const int row0 = blockIdx.x * 8;
    const int t = threadIdx.x;
    const int w = t >> 5, lane = t & 31;

    float acc[4];
#pragma unroll
    for (int v = 0; v < 4; ++v) acc[v] = -INFINITY;

    for (int j0 = 0; j0 < J; j0 += 16) {
        if (t < 128) {
            int jj = t >> 3, r = t & 7;
            int gj = min(j0 + jj, J - 1);
            int gr = min(row0 + r, R - 1);
            Xs[jj * 8 + r] = X[(size_t)gr * ldx + gj];
        }
        if (NT) {
            int i = t >> 1, jq = (t & 1) * 8;
            const float* wrp = Wg + (size_t)i * J + j0 + jq;
            float4 a = *(const float4*)wrp;
            float4 c = *(const float4*)(wrp + 4);
            Ws[(jq + 0) * 128 + i] = a.x;
            Ws[(jq + 1) * 128 + i] = a.y;
            Ws[(jq + 2) * 128 + i] = a.z;
            Ws[(jq + 3) * 128 + i] = a.w;
            Ws[(jq + 4) * 128 + i] = c.x;
            Ws[(jq + 5) * 128 + i] = c.y;
            Ws[(jq + 6) * 128 + i] = c.z;
            Ws[(jq + 7) * 128 + i] = c.w;
        } else {
            const float* W = Wg + (size_t)b * (Nn * Dn);
#pragma unroll
            for (int rep = 0; rep < 2; ++rep) {
                int jj = (t >> 5) + rep * 8;
                int gj = min(j0 + jj, J - 1);
                float4 a = *(const float4*)(W + (size_t)gj * 128 + lane * 4);
                *(float4*)&Ws[jj * 128 + lane * 4] = a;
            }
        }
        __syncthreads();

#pragma unroll
        for (int jj = 0; jj < 16; ++jj) {
            float xv = Xs[jj * 8 + w];
            float4 wv = *(const float4*)&Ws[jj * 128 + lane * 4];
            acc[0] = fmaxf(acc[0], xv + wv.x);
            acc[1] = fmaxf(acc[1], xv + wv.y);
            acc[2] = fmaxf(acc[2], xv + wv.z);
            acc[3] = fmaxf(acc[3], xv + wv.w);
        }
        __syncthreads();
    }

    int rr = row0 + w;
    float rmx = fmaxf(fmaxf(acc[0], acc[1]), fmaxf(acc[2], acc[3]));
#pragma unroll
    for (int o = 16; o > 0; o >>= 1)
        rmx = fmaxf(rmx, __shfl_xor_sync(0xffffffffu, rmx, o));
    if (rr < R) {
        float* hr = H + (size_t)rr * 128 + lane * 4;
        float4 h = *(const float4*)hr;
        h.x = fmaxf(h.x, acc[0] - rmx);
        h.y = fmaxf(h.y, acc[1] - rmx);
        h.z = fmaxf(h.z, acc[2] - rmx);
        h.w = fmaxf(h.w, acc[3] - rmx);
        *(float4*)hr = h;
    }
}

// ---------------- pooled + head + scale ----------------
__global__ void head_k(const float* __restrict__ headW, const float* __restrict__ lsc,
                       float* __restrict__ out) {
    __shared__ float pooled[2][Dn];
    int b = blockIdx.x, chunk = blockIdx.y, t = threadIdx.x;
    {
        int half = t >> 7, d = t & 127;
        float mx = -INFINITY;
        const float* hb = g_H + (size_t)b * Nn * Dn + d;
        int n0 = half * 98;
        for (int n = n0; n < n0 + 98; ++n) mx = fmaxf(mx, hb[(size_t)n * Dn]);
        pooled[half][d] = mx;
    }
    __syncthreads();
    if (t < Dn) pooled[0][t] = fmaxf(pooled[0][t], pooled[1][t]);
    __syncthreads();
    float s = __ldg(lsc);
    int c = chunk * 256 + t;
    if (c < Cn) {
        const float* wr = headW + (size_t)c * Dn;
        float mx = -INFINITY;
#pragma unroll 4
        for (int d = 0; d < Dn; ++d) mx = fmaxf(mx, pooled[0][d] + wr[d]);
        out[(size_t)b * Cn + c] = mx * s;
    }
}

} // namespace

// ---------------- driver ----------------
extern "C" void kernel_launch(void* const* d_in, const int* in_sizes, int n_in,
                              void* d_out, int out_size) {
    (void)in_sizes; (void)n_in; (void)out_size;
    const float* x      = (const float*)d_in[0];
    const float* embedW = (const float*)d_in[1];
    const float* pos    = (const float*)d_in[2];
    const float* qW[2]  = {(const float*)d_in[3],  (const float*)d_in[9]};
    const float* kW[2]  = {(const float*)d_in[4],  (const float*)d_in[10]};
    const float* vW[2]  = {(const float*)d_in[5],  (const float*)d_in[11]};
    const float* f1W[2] = {(const float*)d_in[6],  (const float*)d_in[12]};
    const float* f2W[2] = {(const float*)d_in[7],  (const float*)d_in[13]};
    const float* tau[2] = {(const float*)d_in[8],  (const float*)d_in[14]};
    const float* headW  = (const float*)d_in[15];
    const float* lsc    = (const float*)d_in[16];
    float* out = (float*)d_out;

    void *pH, *pQKV, *pS, *pFFH, *pWq;
    cudaGetSymbolAddress(&pH,   g_H);
    cudaGetSymbolAddress(&pQKV, g_QKV);
    cudaGetSymbolAddress(&pS,   g_S);
    cudaGetSymbolAddress(&pFFH, g_FFH);
    cudaGetSymbolAddress(&pWq,  g_Wqkv);

    const float* fH   = (const float*)pH;
    const float* fQKV = (const float*)pQKV;
    const float* fS   = (const float*)pS;
    const float* fFFH = (const float*)pFFH;

    W6 w6;
    w6.p[0] = qW[0]; w6.p[1] = kW[0]; w6.p[2] = vW[0];
    w6.p[3] = qW[1]; w6.p[4] = kW[1]; w6.p[5] = vW[1];
    prep_k<<<384, 256>>>(w6);

    // embed: H = tropmm(patches(x), embedW) + pos   (patchify fused; grid 196)
    tg32<1, 32><<<dim3(4, 49, 1), 128>>>(nullptr, embedW, (float*)pH,
        RALL, Dn, 256, 0, 0, 0, pos, nullptr, x);

    for (int l = 0; l < 2; ++l) {
        // q,k,v = tropmm(H, W) - rowmax(H)          (grid 294)
        tg32<2, 64><<<dim3(2, 49, 3), 128>>>(fH,
            (const float*)pWq + (size_t)l * 3 * Dn * Dn, (float*)pQKV,
            RALL, Dn, Dn, 0, Dn * Dn, RALL * Dn, nullptr, nullptr, nullptr);
        // S[b,i,j] = max_d(q_id + k_jd)             (grid 392)
        tg32<0, 32><<<dim3(7, 7, 8), 128>>>(fQKV, fQKV + (size_t)RALL * Dn, (float*)pS,
            Nn, Nn, Dn, Nn * Dn, Nn * Dn, Nn * Nn, nullptr, nullptr, nullptr);
        // Z = max_j(S + v); H = max(H, Z - rowmax Z) (grid 200)
        tgfw<false><<<dim3(25, 8), 256>>>(fS, fQKV + (size_t)2 * RALL * Dn, (float*)pH,
            Nn, Nn, Nn, Nn * Nn, Nn * Dn);
        // FFH = max(tropmm(H, f1) - rowmax(H), tau) (grid 196)
        tg32<3, 64><<<dim3(4, 49, 1), 128>>>(fH, f1W[l], (float*)pFFH,
            RALL, DFFn, Dn, 0, 0, 0, nullptr, tau[l], nullptr);
        // Z = tropmm(FFH, f2); H = max(H, Z - rowmax Z)  (grid 196)
        tgfw<true><<<dim3(196, 1), 256>>>(fFFH, f2W[l], (float*)pH,
            RALL, DFFn, DFFn, 0, 0);
    }

    head_k<<<dim3(8, 4), 256>>>(headW, lsc, out);
}